// round 3
// baseline (speedup 1.0000x reference)
#include <cuda_runtime.h>
#include <cuda_bf16.h>

// Problem constants
#define B_ROWS 16384
#define DIM    768
#define ATTRS  51
#define NPAD   64
#define BN_EPS 1e-5f

// GEMM tiling
#define BM 128
#define BN 64
#define BK 16
#define XS2 264         // floats per k-row of duplicated x tile (256 data + 8 pad)
#define NKT (DIM / BK)  // 48
#define GRID_M (B_ROWS / BM)  // 128

typedef unsigned long long u64;

// ---- packed f32x2 helpers (sm_103a FFMA2 — only reachable via PTX) ----
__device__ __forceinline__ void fma2(u64& d, u64 a, u64 b) {
    asm("fma.rn.f32x2 %0, %1, %2, %0;" : "+l"(d) : "l"(a), "l"(b));
}
__device__ __forceinline__ u64 dup2(float v) {
    u64 r; asm("mov.b64 %0, {%1, %1};" : "=l"(r) : "f"(v)); return r;
}
__device__ __forceinline__ float2 unpk(u64 v) {
    float2 r; asm("mov.b64 {%0, %1}, %2;" : "=f"(r.x), "=f"(r.y) : "l"(v)); return r;
}

// -------- device scratch (no allocations allowed) --------
__device__ float g_wc[DIM * NPAD];            // Wc^T, [k][n] padded
__device__ float g_z[B_ROWS * NPAD];          // padded logits (bias-free)
__device__ float g_psum[GRID_M * NPAD];
__device__ float g_psq[GRID_M * NPAD];
__device__ float g_a[NPAD];                   // rstd*gamma
__device__ float g_b[NPAD];                   // beta - mean*rstd*gamma

// ============================================================
// Kernel A: Wc^T[k][a] = sum_j W_attr[a][j] * W_embed[j][k]
// grid (6 k-chunks of 128, 16 a-groups of 4), 128 threads
// a-interleaved smem so FFMA2 pairs (a0,a1),(a2,a3) load as u64.
// ============================================================
__global__ __launch_bounds__(128) void wc_kernel(const float* __restrict__ W_embed,
                                                 const float* __restrict__ W_attr) {
    __shared__ __align__(16) float s_wi[4 * DIM];   // [j][aa] interleaved
    const int k  = blockIdx.x * 128 + threadIdx.x;  // 0..767
    const int a0 = blockIdx.y * 4;                  // 0..60

    for (int i = threadIdx.x; i < 4 * DIM; i += 128) {
        int aa = i & 3, j = i >> 2;
        int a  = a0 + aa;
        s_wi[i] = (a < ATTRS) ? W_attr[a * DIM + j] : 0.0f;
    }
    __syncthreads();

    u64 acc01 = 0ull, acc23 = 0ull;
#pragma unroll 8
    for (int j = 0; j < DIM; j++) {
        u64 wed = dup2(W_embed[j * DIM + k]);        // coalesced + dup
        fma2(acc01, *(const u64*)&s_wi[j * 4    ], wed);
        fma2(acc23, *(const u64*)&s_wi[j * 4 + 2], wed);
    }
    float2 p0 = unpk(acc01), p1 = unpk(acc23);
    float* dst = g_wc + k * NPAD + a0;
    dst[0] = p0.x; dst[1] = p0.y; dst[2] = p1.x; dst[3] = p1.y;
}

// ============================================================
// Kernel B: z = x @ Wc^T  (M=16384, N=64pad, K=768), FFMA2 core
// 512 threads, grid 128.  x-tile stored DUPLICATED (a,a) in smem
// so the broadcast operand of fma.rn.f32x2 is a plain LDS.
// ============================================================
__global__ __launch_bounds__(512) void gemm_kernel(const float* __restrict__ x) {
    __shared__ __align__(16) float xs[BK * XS2];    // 16.9 KB, duplicated rows
    __shared__ __align__(16) float ws[BK * BN];     // 4 KB
    __shared__ float ssum[BN];
    __shared__ float ssq[BN];

    const int tid  = threadIdx.x;
    const int row0 = blockIdx.x * BM;

    if (tid < BN) { ssum[tid] = 0.0f; ssq[tid] = 0.0f; }

    // x tile global-load mapping: 1 float4 per thread
    const int lr = tid >> 2;          // 0..127
    const int lk = (tid & 3) * 4;     // 0,4,8,12
    // w tile global-load mapping: first 256 threads, 1 float4 each
    const int wk = tid >> 4;          // 0..15 (valid when tid<256)
    const int wn = (tid & 15) * 4;
    // compute mapping: 4 rows x 4 cols per thread
    const int tm0 = (tid >> 4) * 4;   // 0..124
    const int tn0 = (tid & 15) * 4;

    const float* xg = x + (size_t)row0 * DIM;

    u64 acc[4][2];
#pragma unroll
    for (int i = 0; i < 4; i++) { acc[i][0] = 0ull; acc[i][1] = 0ull; }

    // prologue: tile 0
    float4 xa = *(const float4*)(xg + (size_t)lr * DIM + lk);
    float4 wa;
    if (tid < 256) wa = *(const float4*)(g_wc + wk * NPAD + wn);

    xs[(lk + 0) * XS2 + 2 * lr]     = xa.x;  xs[(lk + 0) * XS2 + 2 * lr + 1] = xa.x;
    xs[(lk + 1) * XS2 + 2 * lr]     = xa.y;  xs[(lk + 1) * XS2 + 2 * lr + 1] = xa.y;
    xs[(lk + 2) * XS2 + 2 * lr]     = xa.z;  xs[(lk + 2) * XS2 + 2 * lr + 1] = xa.z;
    xs[(lk + 3) * XS2 + 2 * lr]     = xa.w;  xs[(lk + 3) * XS2 + 2 * lr + 1] = xa.w;
    if (tid < 256) *(float4*)(ws + wk * BN + wn) = wa;
    __syncthreads();

    for (int kt = 0; kt < NKT; kt++) {
        // prefetch next tile into registers (overlaps compute)
        if (kt + 1 < NKT) {
            int k0 = (kt + 1) * BK;
            xa = *(const float4*)(xg + (size_t)lr * DIM + k0 + lk);
            if (tid < 256) wa = *(const float4*)(g_wc + (k0 + wk) * NPAD + wn);
        }

#pragma unroll
        for (int k = 0; k < BK; k++) {
            const ulonglong2 a01 = *(const ulonglong2*)&xs[k * XS2 + 2 * tm0];      // rows 0,1 dup'd
            const ulonglong2 a23 = *(const ulonglong2*)&xs[k * XS2 + 2 * tm0 + 4];  // rows 2,3 dup'd
            const ulonglong2 bp  = *(const ulonglong2*)&ws[k * BN + tn0];           // col pairs
            fma2(acc[0][0], a01.x, bp.x);  fma2(acc[0][1], a01.x, bp.y);
            fma2(acc[1][0], a01.y, bp.x);  fma2(acc[1][1], a01.y, bp.y);
            fma2(acc[2][0], a23.x, bp.x);  fma2(acc[2][1], a23.x, bp.y);
            fma2(acc[3][0], a23.y, bp.x);  fma2(acc[3][1], a23.y, bp.y);
        }
        __syncthreads();

        if (kt + 1 < NKT) {
            xs[(lk + 0) * XS2 + 2 * lr]     = xa.x;  xs[(lk + 0) * XS2 + 2 * lr + 1] = xa.x;
            xs[(lk + 1) * XS2 + 2 * lr]     = xa.y;  xs[(lk + 1) * XS2 + 2 * lr + 1] = xa.y;
            xs[(lk + 2) * XS2 + 2 * lr]     = xa.z;  xs[(lk + 2) * XS2 + 2 * lr + 1] = xa.z;
            xs[(lk + 3) * XS2 + 2 * lr]     = xa.w;  xs[(lk + 3) * XS2 + 2 * lr + 1] = xa.w;
            if (tid < 256) *(float4*)(ws + wk * BN + wn) = wa;
            __syncthreads();
        }
    }

    // epilogue: unpack, store z (float4), BN partials
    float va[4][4];
#pragma unroll
    for (int i = 0; i < 4; i++) {
        float2 p0 = unpk(acc[i][0]), p1 = unpk(acc[i][1]);
        va[i][0] = p0.x; va[i][1] = p0.y; va[i][2] = p1.x; va[i][3] = p1.y;
        *(float4*)(g_z + (size_t)(row0 + tm0 + i) * NPAD + tn0) =
            make_float4(p0.x, p0.y, p1.x, p1.y);
    }
#pragma unroll
    for (int j = 0; j < 4; j++) {
        float s = 0.f, q = 0.f;
#pragma unroll
        for (int i = 0; i < 4; i++) {
            float v = va[i][j];
            s += v;
            q = fmaf(v, v, q);
        }
        // lanes l and l^16 share tn0 -> combine before atomics
        s += __shfl_xor_sync(0xffffffffu, s, 16);
        q += __shfl_xor_sync(0xffffffffu, q, 16);
        if ((tid & 16) == 0) {
            atomicAdd(&ssum[tn0 + j], s);
            atomicAdd(&ssq[tn0 + j], q);
        }
    }
    __syncthreads();
    if (tid < BN) {
        g_psum[blockIdx.x * NPAD + tid] = ssum[tid];
        g_psq[blockIdx.x * NPAD + tid]  = ssq[tid];
    }
}

// ============================================================
// Kernel C1: reduce partials -> fused scale/shift (1 block, 64 thr)
// ============================================================
__global__ void stats_kernel(const float* __restrict__ gamma,
                             const float* __restrict__ beta) {
    int n = threadIdx.x;   // 0..63
    float s = 0.f, q = 0.f;
    for (int b = 0; b < GRID_M; b++) {
        s += g_psum[b * NPAD + n];
        q += g_psq[b * NPAD + n];
    }
    const float inv = 1.0f / (float)B_ROWS;
    float mean = s * inv;
    float var  = q * inv - mean * mean;
    float rstd = rsqrtf(var + BN_EPS);
    float gm   = (n < ATTRS) ? gamma[n] : 0.0f;
    float bt   = (n < ATTRS) ? beta[n]  : 0.0f;
    float a = rstd * gm;
    g_a[n] = a;
    g_b[n] = bt - mean * a;
}

// ============================================================
// Kernel C2: y = z * a[n] + b[n] -> d_out [B,51]
// ============================================================
__global__ __launch_bounds__(256) void norm_kernel(float* __restrict__ out) {
    int idx = blockIdx.x * 256 + threadIdx.x;
    if (idx >= B_ROWS * ATTRS) return;
    int row = idx / ATTRS;
    int n   = idx - row * ATTRS;
    float z = g_z[(size_t)row * NPAD + n];
    out[idx] = fmaf(z, g_a[n], g_b[n]);
}

// ============================================================
extern "C" void kernel_launch(void* const* d_in, const int* in_sizes, int n_in,
                              void* d_out, int out_size) {
    const float* x       = (const float*)d_in[0];
    const float* W_embed = (const float*)d_in[1];
    // d_in[2] = b_embed  (cancelled exactly by BatchNorm mean-subtraction)
    const float* W_attr  = (const float*)d_in[3];
    // d_in[4] = b_attr   (cancelled exactly by BatchNorm mean-subtraction)
    const float* gamma   = (const float*)d_in[5];
    const float* beta    = (const float*)d_in[6];
    float* out = (float*)d_out;

    wc_kernel<<<dim3(6, 16), 128>>>(W_embed, W_attr);
    gemm_kernel<<<GRID_M, 512>>>(x);
    stats_kernel<<<1, 64>>>(gamma, beta);
    norm_kernel<<<(B_ROWS * ATTRS + 255) / 256, 256>>>(out);
}

// round 6
// speedup vs baseline: 2.4399x; 2.4399x over previous
#include <cuda_runtime.h>
#include <cuda_bf16.h>
#include <cstdint>

typedef unsigned int u32;
typedef unsigned long long u64;

// Problem constants
#define B_ROWS 16384
#define DIM    768
#define ATTRS  51
#define NPAD   64
#define BN_EPS 1e-5f
#define GRID_M 128            // 16384 / 128 rows per CTA
#define NKS    48             // 768 / 16 k-steps
#define BP_U32 24576          // 48*8*32*2 packed u32 per (hi|lo) half
#define SMEM_DYN 196608       // 2 * BP_U32 * 4 bytes

// -------- device scratch --------
__device__ float g_wcp[4 * NPAD * DIM];          // [q][a][k] j-partials
__device__ __align__(16) u32 g_bp[2 * BP_U32];   // packed B frags: [hi | lo]
__device__ float g_z[B_ROWS * NPAD];             // logits (bias-free, padded)
__device__ float g_psum[GRID_M * NPAD];
__device__ float g_psq[GRID_M * NPAD];
__device__ float g_a[NPAD];                      // rstd*gamma
__device__ float g_b[NPAD];                      // beta - mean*rstd*gamma

// pack bf16x2, memory order (lo,hi)
__device__ __forceinline__ u32 bf16x2(float lo, float hi) {
    u32 r; asm("cvt.rn.bf16x2.f32 %0, %1, %2;" : "=r"(r) : "f"(hi), "f"(lo)); return r;
}
// split a float2 into bf16x2 hi + bf16x2 lo (residual)
__device__ __forceinline__ void split2(float2 v, u32& h, u32& l) {
    h = bf16x2(v.x, v.y);
    float f0 = __uint_as_float(h << 16);
    float f1 = __uint_as_float(h & 0xFFFF0000u);
    l = bf16x2(v.x - f0, v.y - f1);
}
// D += A(16x16 bf16) * B(16x8 bf16), fp32 accum
__device__ __forceinline__ void mma16816(float* c, const u32* a, u32 b0, u32 b1) {
    asm volatile(
        "mma.sync.aligned.m16n8k16.row.col.f32.bf16.bf16.f32 "
        "{%0,%1,%2,%3}, {%4,%5,%6,%7}, {%8,%9}, {%0,%1,%2,%3};"
        : "+f"(c[0]), "+f"(c[1]), "+f"(c[2]), "+f"(c[3])
        : "r"(a[0]), "r"(a[1]), "r"(a[2]), "r"(a[3]), "r"(b0), "r"(b1));
}

// ============================================================
// wc1: j-partial Wc[a][k] = sum over 192 j's of W_attr[a][j]*W_embed[j][k]
// grid (6 k-blocks, 16 a-groups, 4 j-quarters), 128 threads
// ============================================================
__global__ __launch_bounds__(128) void wc1_kernel(const float* __restrict__ W_embed,
                                                  const float* __restrict__ W_attr) {
    __shared__ float s_wa[4 * 192];
    const int k  = blockIdx.x * 128 + threadIdx.x;
    const int a0 = blockIdx.y * 4;
    const int j0 = blockIdx.z * 192;

    for (int i = threadIdx.x; i < 4 * 192; i += 128) {
        int aa = i / 192, j = i - aa * 192;
        int a  = a0 + aa;
        s_wa[i] = (a < ATTRS) ? W_attr[a * DIM + j0 + j] : 0.0f;
    }
    __syncthreads();

    float acc0 = 0.f, acc1 = 0.f, acc2 = 0.f, acc3 = 0.f;
#pragma unroll 16
    for (int j = 0; j < 192; ++j) {
        float we = W_embed[(size_t)(j0 + j) * DIM + k];
        acc0 = fmaf(s_wa[j      ], we, acc0);
        acc1 = fmaf(s_wa[192 + j], we, acc1);
        acc2 = fmaf(s_wa[384 + j], we, acc2);
        acc3 = fmaf(s_wa[576 + j], we, acc3);
    }
    float* dst = g_wcp + (size_t)blockIdx.z * NPAD * DIM;
    dst[(a0 + 0) * DIM + k] = acc0;
    dst[(a0 + 1) * DIM + k] = acc1;
    dst[(a0 + 2) * DIM + k] = acc2;
    dst[(a0 + 3) * DIM + k] = acc3;
}

// ============================================================
// wc2: combine 4 partials, split bf16 hi/lo, scatter into
// mma.sync B-fragment layout:
//   b reg h of lane t, n-tile nt, k-step ks holds
//   { B[16ks + 8h + (t%4)*2][8nt + t/4], B[...+1][...] }
// ============================================================
__global__ __launch_bounds__(256) void wc2_kernel() {
    int idx = blockIdx.x * 256 + threadIdx.x;     // 0..24575
    if (idx >= NPAD * DIM / 2) return;
    int n  = idx / 384;                           // 0..63
    int kp = idx - n * 384;
    int k  = kp * 2;
    size_t i0 = (size_t)n * DIM + k;
    const size_t S = (size_t)NPAD * DIM;
    float s0 = g_wcp[i0]     + g_wcp[S + i0]     + g_wcp[2*S + i0]     + g_wcp[3*S + i0];
    float s1 = g_wcp[i0 + 1] + g_wcp[S + i0 + 1] + g_wcp[2*S + i0 + 1] + g_wcp[3*S + i0 + 1];
    u32 h = bf16x2(s0, s1);
    float f0 = __uint_as_float(h << 16);
    float f1 = __uint_as_float(h & 0xFFFF0000u);
    u32 l = bf16x2(s0 - f0, s1 - f1);

    int ks = k >> 4;
    int hh = (k >> 3) & 1;
    int t  = (n & 7) * 4 + ((k & 7) >> 1);
    int nt = n >> 3;
    int o  = ((ks * 8 + nt) * 32 + t) * 2 + hh;
    g_bp[o]           = h;
    g_bp[BP_U32 + o]  = l;
}

// ============================================================
// GEMM: z = x @ Wc^T via mma.sync bf16 hi/lo split (3 products).
// grid 128, 256 threads = 8 warps; warp w owns rows [w*16, w*16+16),
// full N=64. B staged once in smem (192KB, fragment-linear).
// A fragments loaded directly from gmem fp32 + split in registers.
// No __syncthreads in the mainloop.
// ============================================================
extern __shared__ __align__(16) char dsm[];

__global__ __launch_bounds__(256) void gemm_kernel(const float* __restrict__ x) {
    const int tid  = threadIdx.x;
    const int warp = tid >> 5, lane = tid & 31;

    // ---- stage packed B into smem (uint4 copy, 12288 total) ----
    {
        const uint4* src = (const uint4*)g_bp;
        uint4* dst = (uint4*)dsm;
#pragma unroll
        for (int i = 0; i < 48; ++i)
            dst[tid + i * 256] = src[tid + i * 256];
    }
    __syncthreads();
    const uint2* sb = (const uint2*)dsm;   // [ (ks*8+nt)*32 + lane ], lo at +12288

    const int r0 = blockIdx.x * 128 + warp * 16 + (lane >> 2);
    const float* xr0 = x + (size_t)r0 * DIM + (lane & 3) * 2;
    const float* xr8 = xr0 + 8 * DIM;

    float acc[8][4];
#pragma unroll
    for (int i = 0; i < 8; ++i)
#pragma unroll
        for (int j = 0; j < 4; ++j) acc[i][j] = 0.0f;

    // A fragment prefetch, depth 2
    float2 pf[2][4];
#pragma unroll
    for (int p = 0; p < 2; ++p) {
        int kc = p * 16;
        pf[p][0] = *(const float2*)(xr0 + kc);
        pf[p][1] = *(const float2*)(xr0 + kc + 8);
        pf[p][2] = *(const float2*)(xr8 + kc);
        pf[p][3] = *(const float2*)(xr8 + kc + 8);
    }

#pragma unroll 2
    for (int ks = 0; ks < NKS; ++ks) {
        float2 c0 = pf[ks & 1][0], c1 = pf[ks & 1][1];
        float2 c2 = pf[ks & 1][2], c3 = pf[ks & 1][3];
        if (ks + 2 < NKS) {
            int kc = (ks + 2) * 16;
            pf[ks & 1][0] = *(const float2*)(xr0 + kc);
            pf[ks & 1][1] = *(const float2*)(xr0 + kc + 8);
            pf[ks & 1][2] = *(const float2*)(xr8 + kc);
            pf[ks & 1][3] = *(const float2*)(xr8 + kc + 8);
        }
        // frag order: a0=(r,k0..7) a1=(r+8,k0..7) a2=(r,k8..15) a3=(r+8,k8..15)
        u32 ah[4], al[4];
        split2(c0, ah[0], al[0]);
        split2(c2, ah[1], al[1]);
        split2(c1, ah[2], al[2]);
        split2(c3, ah[3], al[3]);

        const uint2* bp = sb + ks * 256 + lane;
#pragma unroll
        for (int nt = 0; nt < 8; ++nt) {
            uint2 bh = bp[nt * 32];
            uint2 bl = bp[nt * 32 + 12288];
            mma16816(acc[nt], ah, bh.x, bh.y);
            mma16816(acc[nt], ah, bl.x, bl.y);
            mma16816(acc[nt], al, bh.x, bh.y);
        }
    }

    // ---- epilogue: store z + BN partials (reuse smem) ----
    __syncthreads();
    float* ssum = (float*)dsm;
    float* ssq  = ssum + NPAD;
    if (tid < 2 * NPAD) ssum[tid] = 0.0f;
    __syncthreads();

    float* zr = g_z + (size_t)r0 * NPAD;
#pragma unroll
    for (int nt = 0; nt < 8; ++nt) {
        int n0 = nt * 8 + (lane & 3) * 2;
        *(float2*)(zr + n0)            = make_float2(acc[nt][0], acc[nt][1]);
        *(float2*)(zr + 8 * NPAD + n0) = make_float2(acc[nt][2], acc[nt][3]);
        float s0 = acc[nt][0] + acc[nt][2];
        float s1 = acc[nt][1] + acc[nt][3];
        float q0 = fmaf(acc[nt][0], acc[nt][0], acc[nt][2] * acc[nt][2]);
        float q1 = fmaf(acc[nt][1], acc[nt][1], acc[nt][3] * acc[nt][3]);
#pragma unroll
        for (int m = 4; m <= 16; m <<= 1) {
            s0 += __shfl_xor_sync(0xffffffffu, s0, m);
            s1 += __shfl_xor_sync(0xffffffffu, s1, m);
            q0 += __shfl_xor_sync(0xffffffffu, q0, m);
            q1 += __shfl_xor_sync(0xffffffffu, q1, m);
        }
        if (lane < 4) {
            atomicAdd(&ssum[n0], s0);     atomicAdd(&ssum[n0 + 1], s1);
            atomicAdd(&ssq[n0], q0);      atomicAdd(&ssq[n0 + 1], q1);
        }
    }
    __syncthreads();
    if (tid < NPAD) {
        g_psum[blockIdx.x * NPAD + tid] = ssum[tid];
        g_psq[blockIdx.x * NPAD + tid]  = ssq[tid];
    }
}

// ============================================================
// stats: reduce partials -> fused scale/shift
// ============================================================
__global__ void stats_kernel(const float* __restrict__ gamma,
                             const float* __restrict__ beta) {
    int n = threadIdx.x;   // 0..63
    float s = 0.f, q = 0.f;
#pragma unroll 8
    for (int b = 0; b < GRID_M; ++b) {
        s += g_psum[b * NPAD + n];
        q += g_psq[b * NPAD + n];
    }
    const float inv = 1.0f / (float)B_ROWS;
    float mean = s * inv;
    float var  = q * inv - mean * mean;
    float rstd = rsqrtf(var + BN_EPS);
    float gm = (n < ATTRS) ? gamma[n] : 0.0f;
    float bt = (n < ATTRS) ? beta[n]  : 0.0f;
    float a = rstd * gm;
    g_a[n] = a;
    g_b[n] = bt - mean * a;
}

// ============================================================
// norm: y = z*a[n] + b[n] -> d_out [B,51]
// 204*512*8 = 835584 = 16384*51 exactly
// ============================================================
__global__ __launch_bounds__(512) void norm_kernel(float* __restrict__ out) {
    const int b0 = blockIdx.x * 512 + threadIdx.x;
#pragma unroll
    for (int i = 0; i < 8; ++i) {
        int idx = b0 + i * 104448;
        int row = idx / ATTRS;
        int n   = idx - row * ATTRS;
        out[idx] = fmaf(g_z[(size_t)row * NPAD + n], g_a[n], g_b[n]);
    }
}

// ============================================================
extern "C" void kernel_launch(void* const* d_in, const int* in_sizes, int n_in,
                              void* d_out, int out_size) {
    const float* x       = (const float*)d_in[0];
    const float* W_embed = (const float*)d_in[1];
    // d_in[2] = b_embed  (cancelled exactly by BatchNorm mean-subtraction)
    const float* W_attr  = (const float*)d_in[3];
    // d_in[4] = b_attr   (cancelled exactly by BatchNorm mean-subtraction)
    const float* gamma   = (const float*)d_in[5];
    const float* beta    = (const float*)d_in[6];
    float* out = (float*)d_out;

    cudaFuncSetAttribute(gemm_kernel, cudaFuncAttributeMaxDynamicSharedMemorySize, SMEM_DYN);

    wc1_kernel<<<dim3(6, 16, 4), 128>>>(W_embed, W_attr);
    wc2_kernel<<<96, 256>>>();
    gemm_kernel<<<GRID_M, 256, SMEM_DYN>>>(x);
    stats_kernel<<<1, 64>>>(gamma, beta);
    norm_kernel<<<204, 512>>>(out);
}

// round 7
// speedup vs baseline: 2.5529x; 1.0463x over previous
#include <cuda_runtime.h>
#include <cuda_bf16.h>
#include <cstdint>

typedef unsigned int u32;
typedef unsigned long long u64;

// Problem constants
#define B_ROWS 16384
#define DIM    768
#define ATTRS  51
#define NPAD   64
#define BN_EPS 1e-5f
#define GRID_M 128            // 16384 / 128 rows per CTA
#define NKS    48             // 768 / 16 k-steps
#define BP_U32 24576          // 48*8*32*2 packed u32 per (hi|lo) half
#define SMEM_DYN 196608       // 2 * BP_U32 * 4 bytes

// -------- device scratch --------
__device__ float g_wcp[4 * NPAD * DIM];          // [q][a][k] j-partials
__device__ __align__(16) u32 g_bp[2 * BP_U32];   // packed B frags: [hi | lo]
__device__ float g_z[B_ROWS * NPAD];             // logits (bias-free, padded)
__device__ float g_psum[GRID_M * NPAD];
__device__ float g_psq[GRID_M * NPAD];
__device__ float g_a[NPAD];                      // rstd*gamma
__device__ float g_b[NPAD];                      // beta - mean*rstd*gamma

// pack bf16x2, memory order (lo,hi)
__device__ __forceinline__ u32 bf16x2(float lo, float hi) {
    u32 r; asm("cvt.rn.bf16x2.f32 %0, %1, %2;" : "=r"(r) : "f"(hi), "f"(lo)); return r;
}
// split a float2 into bf16x2 hi + bf16x2 lo (residual)
__device__ __forceinline__ void split2(float2 v, u32& h, u32& l) {
    h = bf16x2(v.x, v.y);
    float f0 = __uint_as_float(h << 16);
    float f1 = __uint_as_float(h & 0xFFFF0000u);
    l = bf16x2(v.x - f0, v.y - f1);
}
// D += A(16x16 bf16) * B(16x8 bf16), fp32 accum
__device__ __forceinline__ void mma16816(float* c, const u32* a, u32 b0, u32 b1) {
    asm volatile(
        "mma.sync.aligned.m16n8k16.row.col.f32.bf16.bf16.f32 "
        "{%0,%1,%2,%3}, {%4,%5,%6,%7}, {%8,%9}, {%0,%1,%2,%3};"
        : "+f"(c[0]), "+f"(c[1]), "+f"(c[2]), "+f"(c[3])
        : "r"(a[0]), "r"(a[1]), "r"(a[2]), "r"(a[3]), "r"(b0), "r"(b1));
}

// ============================================================
// wc1: j-partial Wc[a][k] = sum over 192 j's of W_attr[a][j]*W_embed[j][k]
// grid (6 k-blocks, 16 a-groups, 4 j-quarters), 128 threads
// ============================================================
__global__ __launch_bounds__(128) void wc1_kernel(const float* __restrict__ W_embed,
                                                  const float* __restrict__ W_attr) {
    __shared__ float s_wa[4 * 192];
    const int k  = blockIdx.x * 128 + threadIdx.x;
    const int a0 = blockIdx.y * 4;
    const int j0 = blockIdx.z * 192;

    for (int i = threadIdx.x; i < 4 * 192; i += 128) {
        int aa = i / 192, j = i - aa * 192;
        int a  = a0 + aa;
        s_wa[i] = (a < ATTRS) ? W_attr[a * DIM + j0 + j] : 0.0f;
    }
    __syncthreads();

    float acc0 = 0.f, acc1 = 0.f, acc2 = 0.f, acc3 = 0.f;
#pragma unroll 16
    for (int j = 0; j < 192; ++j) {
        float we = W_embed[(size_t)(j0 + j) * DIM + k];
        acc0 = fmaf(s_wa[j      ], we, acc0);
        acc1 = fmaf(s_wa[192 + j], we, acc1);
        acc2 = fmaf(s_wa[384 + j], we, acc2);
        acc3 = fmaf(s_wa[576 + j], we, acc3);
    }
    float* dst = g_wcp + (size_t)blockIdx.z * NPAD * DIM;
    dst[(a0 + 0) * DIM + k] = acc0;
    dst[(a0 + 1) * DIM + k] = acc1;
    dst[(a0 + 2) * DIM + k] = acc2;
    dst[(a0 + 3) * DIM + k] = acc3;
}

// ============================================================
// wc2: combine 4 partials, split bf16 hi/lo, scatter into
// mma.sync B-fragment layout
// ============================================================
__global__ __launch_bounds__(256) void wc2_kernel() {
    int idx = blockIdx.x * 256 + threadIdx.x;     // 0..24575
    if (idx >= NPAD * DIM / 2) return;
    int n  = idx / 384;                           // 0..63
    int kp = idx - n * 384;
    int k  = kp * 2;
    size_t i0 = (size_t)n * DIM + k;
    const size_t S = (size_t)NPAD * DIM;
    float s0 = g_wcp[i0]     + g_wcp[S + i0]     + g_wcp[2*S + i0]     + g_wcp[3*S + i0];
    float s1 = g_wcp[i0 + 1] + g_wcp[S + i0 + 1] + g_wcp[2*S + i0 + 1] + g_wcp[3*S + i0 + 1];
    u32 h = bf16x2(s0, s1);
    float f0 = __uint_as_float(h << 16);
    float f1 = __uint_as_float(h & 0xFFFF0000u);
    u32 l = bf16x2(s0 - f0, s1 - f1);

    int ks = k >> 4;
    int hh = (k >> 3) & 1;
    int t  = (n & 7) * 4 + ((k & 7) >> 1);
    int nt = n >> 3;
    int o  = ((ks * 8 + nt) * 32 + t) * 2 + hh;
    g_bp[o]           = h;
    g_bp[BP_U32 + o]  = l;
}

// ============================================================
// GEMM: z = x @ Wc^T via mma.sync bf16 hi/lo split (3 products).
// grid 128, 128 threads = 4 warps; warp w owns 32 rows
// (two 16-row fragment sets) -> B LDS amortized over 2x MMAs.
// B staged once in smem; A loaded from gmem fp32, split in regs.
// No __syncthreads in the mainloop.
// ============================================================
extern __shared__ __align__(16) char dsm[];

__global__ __launch_bounds__(128) void gemm_kernel(const float* __restrict__ x) {
    const int tid  = threadIdx.x;
    const int warp = tid >> 5, lane = tid & 31;

    // ---- stage packed B into smem (uint4 copy, 12288 total) ----
    {
        const uint4* src = (const uint4*)g_bp;
        uint4* dst = (uint4*)dsm;
#pragma unroll
        for (int i = 0; i < 96; ++i)
            dst[tid + i * 128] = src[tid + i * 128];
    }
    __syncthreads();
    const uint2* sb = (const uint2*)dsm;   // [ (ks*8+nt)*32 + lane ], lo at +12288

    // warp owns rows [blk*128 + warp*32, +32): sets {r0,r0+8} and {r0+16,r0+24}
    const int r0 = blockIdx.x * 128 + warp * 32 + (lane >> 2);
    const float* xr0  = x + (size_t)r0 * DIM + (lane & 3) * 2;
    const float* xr8  = xr0 + 8  * DIM;
    const float* xr16 = xr0 + 16 * DIM;
    const float* xr24 = xr0 + 24 * DIM;

    float acc[2][8][4];
#pragma unroll
    for (int h = 0; h < 2; ++h)
#pragma unroll
        for (int i = 0; i < 8; ++i)
#pragma unroll
            for (int j = 0; j < 4; ++j) acc[h][i][j] = 0.0f;

    // A fragment prefetch, depth 2
    float2 pf[2][8];
#pragma unroll
    for (int p = 0; p < 2; ++p) {
        int kc = p * 16;
        pf[p][0] = *(const float2*)(xr0  + kc);
        pf[p][1] = *(const float2*)(xr0  + kc + 8);
        pf[p][2] = *(const float2*)(xr8  + kc);
        pf[p][3] = *(const float2*)(xr8  + kc + 8);
        pf[p][4] = *(const float2*)(xr16 + kc);
        pf[p][5] = *(const float2*)(xr16 + kc + 8);
        pf[p][6] = *(const float2*)(xr24 + kc);
        pf[p][7] = *(const float2*)(xr24 + kc + 8);
    }

#pragma unroll 2
    for (int ks = 0; ks < NKS; ++ks) {
        float2 c[8];
#pragma unroll
        for (int i = 0; i < 8; ++i) c[i] = pf[ks & 1][i];
        if (ks + 2 < NKS) {
            int kc = (ks + 2) * 16;
            pf[ks & 1][0] = *(const float2*)(xr0  + kc);
            pf[ks & 1][1] = *(const float2*)(xr0  + kc + 8);
            pf[ks & 1][2] = *(const float2*)(xr8  + kc);
            pf[ks & 1][3] = *(const float2*)(xr8  + kc + 8);
            pf[ks & 1][4] = *(const float2*)(xr16 + kc);
            pf[ks & 1][5] = *(const float2*)(xr16 + kc + 8);
            pf[ks & 1][6] = *(const float2*)(xr24 + kc);
            pf[ks & 1][7] = *(const float2*)(xr24 + kc + 8);
        }
        // frag order per set: a0=(r,k0..7) a1=(r+8,k0..7) a2=(r,k8..15) a3=(r+8,k8..15)
        u32 ah[2][4], al[2][4];
        split2(c[0], ah[0][0], al[0][0]);
        split2(c[2], ah[0][1], al[0][1]);
        split2(c[1], ah[0][2], al[0][2]);
        split2(c[3], ah[0][3], al[0][3]);
        split2(c[4], ah[1][0], al[1][0]);
        split2(c[6], ah[1][1], al[1][1]);
        split2(c[5], ah[1][2], al[1][2]);
        split2(c[7], ah[1][3], al[1][3]);

        const uint2* bp = sb + ks * 256 + lane;
#pragma unroll
        for (int nt = 0; nt < 8; ++nt) {
            uint2 bh = bp[nt * 32];
            uint2 bl = bp[nt * 32 + 12288];
            mma16816(acc[0][nt], ah[0], bh.x, bh.y);
            mma16816(acc[0][nt], ah[0], bl.x, bl.y);
            mma16816(acc[0][nt], al[0], bh.x, bh.y);
            mma16816(acc[1][nt], ah[1], bh.x, bh.y);
            mma16816(acc[1][nt], ah[1], bl.x, bl.y);
            mma16816(acc[1][nt], al[1], bh.x, bh.y);
        }
    }

    // ---- epilogue: store z + BN partials (reuse smem) ----
    __syncthreads();
    float* ssum = (float*)dsm;
    float* ssq  = ssum + NPAD;
    if (tid < NPAD) { ssum[tid] = 0.0f; ssq[tid] = 0.0f; }
    __syncthreads();

#pragma unroll
    for (int nt = 0; nt < 8; ++nt) {
        int n0 = nt * 8 + (lane & 3) * 2;
        float s0 = 0.f, s1 = 0.f, q0 = 0.f, q1 = 0.f;
#pragma unroll
        for (int h = 0; h < 2; ++h) {
            float* zr = g_z + (size_t)(r0 + 16 * h) * NPAD;
            *(float2*)(zr + n0)            = make_float2(acc[h][nt][0], acc[h][nt][1]);
            *(float2*)(zr + 8 * NPAD + n0) = make_float2(acc[h][nt][2], acc[h][nt][3]);
            s0 += acc[h][nt][0] + acc[h][nt][2];
            s1 += acc[h][nt][1] + acc[h][nt][3];
            q0 += fmaf(acc[h][nt][0], acc[h][nt][0], acc[h][nt][2] * acc[h][nt][2]);
            q1 += fmaf(acc[h][nt][1], acc[h][nt][1], acc[h][nt][3] * acc[h][nt][3]);
        }
#pragma unroll
        for (int m = 4; m <= 16; m <<= 1) {
            s0 += __shfl_xor_sync(0xffffffffu, s0, m);
            s1 += __shfl_xor_sync(0xffffffffu, s1, m);
            q0 += __shfl_xor_sync(0xffffffffu, q0, m);
            q1 += __shfl_xor_sync(0xffffffffu, q1, m);
        }
        if (lane < 4) {
            atomicAdd(&ssum[n0], s0);     atomicAdd(&ssum[n0 + 1], s1);
            atomicAdd(&ssq[n0], q0);      atomicAdd(&ssq[n0 + 1], q1);
        }
    }
    __syncthreads();
    if (tid < NPAD) {
        g_psum[blockIdx.x * NPAD + tid] = ssum[tid];
        g_psq[blockIdx.x * NPAD + tid]  = ssq[tid];
    }
}

// ============================================================
// stats: reduce partials -> fused scale/shift
// 512 threads: 64 cols x 8 row-groups, L2-resident loads
// ============================================================
__global__ __launch_bounds__(512) void stats_kernel(const float* __restrict__ gamma,
                                                    const float* __restrict__ beta) {
    __shared__ float ss[8][NPAD], sq[8][NPAD];
    const int n = threadIdx.x & 63;
    const int g = threadIdx.x >> 6;    // 0..7
    float s = 0.f, q = 0.f;
#pragma unroll
    for (int b = g; b < GRID_M; b += 8) {
        s += g_psum[b * NPAD + n];
        q += g_psq[b * NPAD + n];
    }
    ss[g][n] = s; sq[g][n] = q;
    __syncthreads();
    if (threadIdx.x < NPAD) {
        float S = 0.f, Q = 0.f;
#pragma unroll
        for (int i = 0; i < 8; ++i) { S += ss[i][n]; Q += sq[i][n]; }
        const float inv = 1.0f / (float)B_ROWS;
        float mean = S * inv;
        float var  = Q * inv - mean * mean;
        float rstd = rsqrtf(var + BN_EPS);
        float gm = (n < ATTRS) ? gamma[n] : 0.0f;
        float bt = (n < ATTRS) ? beta[n]  : 0.0f;
        float a = rstd * gm;
        g_a[n] = a;
        g_b[n] = bt - mean * a;
    }
}

// ============================================================
// norm: y = z*a[n] + b[n] -> d_out [B,51]
// 204*512*8 = 835584 = 16384*51 exactly
// ============================================================
__global__ __launch_bounds__(512) void norm_kernel(float* __restrict__ out) {
    const int b0 = blockIdx.x * 512 + threadIdx.x;
#pragma unroll
    for (int i = 0; i < 8; ++i) {
        int idx = b0 + i * 104448;
        int row = idx / ATTRS;
        int n   = idx - row * ATTRS;
        out[idx] = fmaf(g_z[(size_t)row * NPAD + n], g_a[n], g_b[n]);
    }
}

// ============================================================
extern "C" void kernel_launch(void* const* d_in, const int* in_sizes, int n_in,
                              void* d_out, int out_size) {
    const float* x       = (const float*)d_in[0];
    const float* W_embed = (const float*)d_in[1];
    // d_in[2] = b_embed  (cancelled exactly by BatchNorm mean-subtraction)
    const float* W_attr  = (const float*)d_in[3];
    // d_in[4] = b_attr   (cancelled exactly by BatchNorm mean-subtraction)
    const float* gamma   = (const float*)d_in[5];
    const float* beta    = (const float*)d_in[6];
    float* out = (float*)d_out;

    cudaFuncSetAttribute(gemm_kernel, cudaFuncAttributeMaxDynamicSharedMemorySize, SMEM_DYN);

    wc1_kernel<<<dim3(6, 16, 4), 128>>>(W_embed, W_attr);
    wc2_kernel<<<96, 256>>>();
    gemm_kernel<<<GRID_M, 128, SMEM_DYN>>>(x);
    stats_kernel<<<1, 512>>>(gamma, beta);
    norm_kernel<<<204, 512>>>(out);
}

// round 8
// speedup vs baseline: 2.6544x; 1.0398x over previous
#include <cuda_runtime.h>
#include <cuda_bf16.h>
#include <cstdint>

typedef unsigned int u32;
typedef unsigned long long u64;

// Problem constants
#define B_ROWS 16384
#define DIM    768
#define ATTRS  51
#define NPAD   64
#define BN_EPS 1e-5f
#define GRID_M 128            // 16384 / 128 rows per CTA
#define NKS    48             // 768 / 16 k-steps
#define BP_U32 24576          // 48*8*32*2 packed u32 per (hi|lo) half
#define SMEM_DYN 196608       // 2 * BP_U32 * 4 bytes

// -------- device scratch --------
__device__ float g_wcp[4 * NPAD * DIM];          // [q][a][k] j-partials
__device__ __align__(16) u32 g_bp[2 * BP_U32];   // packed B frags: [hi | lo]
__device__ float g_z[B_ROWS * NPAD];             // logits (bias-free, padded)
__device__ float g_psum[GRID_M * NPAD];
__device__ float g_psq[GRID_M * NPAD];
__device__ float g_a[NPAD];                      // rstd*gamma
__device__ float g_b[NPAD];                      // beta - mean*rstd*gamma

// pack bf16x2, memory order (lo,hi)
__device__ __forceinline__ u32 bf16x2(float lo, float hi) {
    u32 r; asm("cvt.rn.bf16x2.f32 %0, %1, %2;" : "=r"(r) : "f"(hi), "f"(lo)); return r;
}
// split a float2 into bf16x2 hi + bf16x2 lo (residual)
__device__ __forceinline__ void split2(float2 v, u32& h, u32& l) {
    h = bf16x2(v.x, v.y);
    float f0 = __uint_as_float(h << 16);
    float f1 = __uint_as_float(h & 0xFFFF0000u);
    l = bf16x2(v.x - f0, v.y - f1);
}
// D += A(16x16 bf16) * B(16x8 bf16), fp32 accum
__device__ __forceinline__ void mma16816(float* c, const u32* a, u32 b0, u32 b1) {
    asm volatile(
        "mma.sync.aligned.m16n8k16.row.col.f32.bf16.bf16.f32 "
        "{%0,%1,%2,%3}, {%4,%5,%6,%7}, {%8,%9}, {%0,%1,%2,%3};"
        : "+f"(c[0]), "+f"(c[1]), "+f"(c[2]), "+f"(c[3])
        : "r"(a[0]), "r"(a[1]), "r"(a[2]), "r"(a[3]), "r"(b0), "r"(b1));
}

// ============================================================
// wc1: j-partial Wc[a][k] = sum over 192 j's of W_attr[a][j]*W_embed[j][k]
// grid (6 k-blocks, 16 a-groups, 4 j-quarters), 128 threads
// ============================================================
__global__ __launch_bounds__(128) void wc1_kernel(const float* __restrict__ W_embed,
                                                  const float* __restrict__ W_attr) {
    __shared__ float s_wa[4 * 192];
    const int k  = blockIdx.x * 128 + threadIdx.x;
    const int a0 = blockIdx.y * 4;
    const int j0 = blockIdx.z * 192;

    for (int i = threadIdx.x; i < 4 * 192; i += 128) {
        int aa = i / 192, j = i - aa * 192;
        int a  = a0 + aa;
        s_wa[i] = (a < ATTRS) ? W_attr[a * DIM + j0 + j] : 0.0f;
    }
    __syncthreads();

    float acc0 = 0.f, acc1 = 0.f, acc2 = 0.f, acc3 = 0.f;
#pragma unroll 16
    for (int j = 0; j < 192; ++j) {
        float we = W_embed[(size_t)(j0 + j) * DIM + k];
        acc0 = fmaf(s_wa[j      ], we, acc0);
        acc1 = fmaf(s_wa[192 + j], we, acc1);
        acc2 = fmaf(s_wa[384 + j], we, acc2);
        acc3 = fmaf(s_wa[576 + j], we, acc3);
    }
    float* dst = g_wcp + (size_t)blockIdx.z * NPAD * DIM;
    dst[(a0 + 0) * DIM + k] = acc0;
    dst[(a0 + 1) * DIM + k] = acc1;
    dst[(a0 + 2) * DIM + k] = acc2;
    dst[(a0 + 3) * DIM + k] = acc3;
}

// ============================================================
// wc2: combine 4 partials, split bf16 hi/lo, scatter into
// mma.sync B-fragment layout
// ============================================================
__global__ __launch_bounds__(256) void wc2_kernel() {
    int idx = blockIdx.x * 256 + threadIdx.x;     // 0..24575
    if (idx >= NPAD * DIM / 2) return;
    int n  = idx / 384;                           // 0..63
    int kp = idx - n * 384;
    int k  = kp * 2;
    size_t i0 = (size_t)n * DIM + k;
    const size_t S = (size_t)NPAD * DIM;
    float s0 = g_wcp[i0]     + g_wcp[S + i0]     + g_wcp[2*S + i0]     + g_wcp[3*S + i0];
    float s1 = g_wcp[i0 + 1] + g_wcp[S + i0 + 1] + g_wcp[2*S + i0 + 1] + g_wcp[3*S + i0 + 1];
    u32 h = bf16x2(s0, s1);
    float f0 = __uint_as_float(h << 16);
    float f1 = __uint_as_float(h & 0xFFFF0000u);
    u32 l = bf16x2(s0 - f0, s1 - f1);

    int ks = k >> 4;
    int hh = (k >> 3) & 1;
    int t  = (n & 7) * 4 + ((k & 7) >> 1);
    int nt = n >> 3;
    int o  = ((ks * 8 + nt) * 32 + t) * 2 + hh;
    g_bp[o]           = h;
    g_bp[BP_U32 + o]  = l;
}

// ============================================================
// GEMM: z = x @ Wc^T via mma.sync bf16 hi/lo split (3 products).
// grid 128, 256 threads = 8 warps; warp w owns rows [w*16, w*16+16),
// full N=64.  (2 warps/SMSP — measured best for latency hiding.)
// B staged once in smem; A from gmem fp32, split in registers.
// No __syncthreads in the mainloop.
// ============================================================
extern __shared__ __align__(16) char dsm[];

__global__ __launch_bounds__(256) void gemm_kernel(const float* __restrict__ x) {
    const int tid  = threadIdx.x;
    const int warp = tid >> 5, lane = tid & 31;

    // ---- stage packed B into smem (uint4 copy, 12288 total) ----
    {
        const uint4* src = (const uint4*)g_bp;
        uint4* dst = (uint4*)dsm;
#pragma unroll
        for (int i = 0; i < 48; ++i)
            dst[tid + i * 256] = src[tid + i * 256];
    }
    __syncthreads();
    const uint2* sb = (const uint2*)dsm;   // [ (ks*8+nt)*32 + lane ], lo at +12288

    const int r0 = blockIdx.x * 128 + warp * 16 + (lane >> 2);
    const float* xr0 = x + (size_t)r0 * DIM + (lane & 3) * 2;
    const float* xr8 = xr0 + 8 * DIM;

    float acc[8][4];
#pragma unroll
    for (int i = 0; i < 8; ++i)
#pragma unroll
        for (int j = 0; j < 4; ++j) acc[i][j] = 0.0f;

    // A fragment prefetch, depth 2
    float2 pf[2][4];
#pragma unroll
    for (int p = 0; p < 2; ++p) {
        int kc = p * 16;
        pf[p][0] = *(const float2*)(xr0 + kc);
        pf[p][1] = *(const float2*)(xr0 + kc + 8);
        pf[p][2] = *(const float2*)(xr8 + kc);
        pf[p][3] = *(const float2*)(xr8 + kc + 8);
    }

#pragma unroll 2
    for (int ks = 0; ks < NKS; ++ks) {
        float2 c0 = pf[ks & 1][0], c1 = pf[ks & 1][1];
        float2 c2 = pf[ks & 1][2], c3 = pf[ks & 1][3];
        if (ks + 2 < NKS) {
            int kc = (ks + 2) * 16;
            pf[ks & 1][0] = *(const float2*)(xr0 + kc);
            pf[ks & 1][1] = *(const float2*)(xr0 + kc + 8);
            pf[ks & 1][2] = *(const float2*)(xr8 + kc);
            pf[ks & 1][3] = *(const float2*)(xr8 + kc + 8);
        }
        // frag order: a0=(r,k0..7) a1=(r+8,k0..7) a2=(r,k8..15) a3=(r+8,k8..15)
        u32 ah[4], al[4];
        split2(c0, ah[0], al[0]);
        split2(c2, ah[1], al[1]);
        split2(c1, ah[2], al[2]);
        split2(c3, ah[3], al[3]);

        const uint2* bp = sb + ks * 256 + lane;
#pragma unroll
        for (int nt = 0; nt < 8; ++nt) {
            uint2 bh = bp[nt * 32];
            uint2 bl = bp[nt * 32 + 12288];
            mma16816(acc[nt], ah, bh.x, bh.y);
            mma16816(acc[nt], ah, bl.x, bl.y);
            mma16816(acc[nt], al, bh.x, bh.y);
        }
    }

    // ---- epilogue: store z + BN partials (reuse smem) ----
    __syncthreads();
    float* ssum = (float*)dsm;
    float* ssq  = ssum + NPAD;
    if (tid < 2 * NPAD) ssum[tid] = 0.0f;
    __syncthreads();

    float* zr = g_z + (size_t)r0 * NPAD;
#pragma unroll
    for (int nt = 0; nt < 8; ++nt) {
        int n0 = nt * 8 + (lane & 3) * 2;
        *(float2*)(zr + n0)            = make_float2(acc[nt][0], acc[nt][1]);
        *(float2*)(zr + 8 * NPAD + n0) = make_float2(acc[nt][2], acc[nt][3]);
        float s0 = acc[nt][0] + acc[nt][2];
        float s1 = acc[nt][1] + acc[nt][3];
        float q0 = fmaf(acc[nt][0], acc[nt][0], acc[nt][2] * acc[nt][2]);
        float q1 = fmaf(acc[nt][1], acc[nt][1], acc[nt][3] * acc[nt][3]);
#pragma unroll
        for (int m = 4; m <= 16; m <<= 1) {
            s0 += __shfl_xor_sync(0xffffffffu, s0, m);
            s1 += __shfl_xor_sync(0xffffffffu, s1, m);
            q0 += __shfl_xor_sync(0xffffffffu, q0, m);
            q1 += __shfl_xor_sync(0xffffffffu, q1, m);
        }
        if (lane < 4) {
            atomicAdd(&ssum[n0], s0);     atomicAdd(&ssum[n0 + 1], s1);
            atomicAdd(&ssq[n0], q0);      atomicAdd(&ssq[n0 + 1], q1);
        }
    }
    __syncthreads();
    if (tid < NPAD) {
        g_psum[blockIdx.x * NPAD + tid] = ssum[tid];
        g_psq[blockIdx.x * NPAD + tid]  = ssq[tid];
    }
}

// ============================================================
// stats: one block per column n (64 blocks, 128 threads);
// thread t reduces partial of row-block t, shuffle+smem combine.
// ============================================================
__global__ __launch_bounds__(128) void stats_kernel(const float* __restrict__ gamma,
                                                    const float* __restrict__ beta) {
    __shared__ float ss[4], sq[4];
    const int n = blockIdx.x;           // 0..63
    const int t = threadIdx.x;          // 0..127
    float s = g_psum[t * NPAD + n];
    float q = g_psq[t * NPAD + n];
#pragma unroll
    for (int m = 16; m >= 1; m >>= 1) {
        s += __shfl_xor_sync(0xffffffffu, s, m);
        q += __shfl_xor_sync(0xffffffffu, q, m);
    }
    if ((t & 31) == 0) { ss[t >> 5] = s; sq[t >> 5] = q; }
    __syncthreads();
    if (t == 0) {
        float S = ss[0] + ss[1] + ss[2] + ss[3];
        float Q = sq[0] + sq[1] + sq[2] + sq[3];
        const float inv = 1.0f / (float)B_ROWS;
        float mean = S * inv;
        float var  = Q * inv - mean * mean;
        float rstd = rsqrtf(var + BN_EPS);
        float gm = (n < ATTRS) ? gamma[n] : 0.0f;
        float bt = (n < ATTRS) ? beta[n]  : 0.0f;
        float a = rstd * gm;
        g_a[n] = a;
        g_b[n] = bt - mean * a;
    }
}

// ============================================================
// norm: y = z*a[n] + b[n] -> d_out [B,51]
// 204*512*8 = 835584 = 16384*51 exactly
// ============================================================
__global__ __launch_bounds__(512) void norm_kernel(float* __restrict__ out) {
    const int b0 = blockIdx.x * 512 + threadIdx.x;
#pragma unroll
    for (int i = 0; i < 8; ++i) {
        int idx = b0 + i * 104448;
        int row = idx / ATTRS;
        int n   = idx - row * ATTRS;
        out[idx] = fmaf(g_z[(size_t)row * NPAD + n], g_a[n], g_b[n]);
    }
}

// ============================================================
extern "C" void kernel_launch(void* const* d_in, const int* in_sizes, int n_in,
                              void* d_out, int out_size) {
    const float* x       = (const float*)d_in[0];
    const float* W_embed = (const float*)d_in[1];
    // d_in[2] = b_embed  (cancelled exactly by BatchNorm mean-subtraction)
    const float* W_attr  = (const float*)d_in[3];
    // d_in[4] = b_attr   (cancelled exactly by BatchNorm mean-subtraction)
    const float* gamma   = (const float*)d_in[5];
    const float* beta    = (const float*)d_in[6];
    float* out = (float*)d_out;

    cudaFuncSetAttribute(gemm_kernel, cudaFuncAttributeMaxDynamicSharedMemorySize, SMEM_DYN);

    wc1_kernel<<<dim3(6, 16, 4), 128>>>(W_embed, W_attr);
    wc2_kernel<<<96, 256>>>();
    gemm_kernel<<<GRID_M, 256, SMEM_DYN>>>(x);
    stats_kernel<<<NPAD, 128>>>(gamma, beta);
    norm_kernel<<<204, 512>>>(out);
}

// round 10
// speedup vs baseline: 2.7732x; 1.0447x over previous
#include <cuda_runtime.h>
#include <cuda_bf16.h>
#include <cstdint>

typedef unsigned int u32;
typedef unsigned long long u64;

// Problem constants
#define B_ROWS 16384
#define DIM    768
#define ATTRS  51
#define NPAD   64
#define BN_EPS 1e-5f
#define GRID_M 128            // 16384 / 128 rows per CTA
#define NKS    48             // 768 / 16 k-steps
#define BP_U4  12288          // 48*8*32 uint4 entries {hi0,hi1,lo0,lo1}
#define SMEM_DYN 196608       // BP_U4 * 16 bytes

// -------- device scratch --------
__device__ float g_wcp[4 * NPAD * DIM];          // [q][a][k] j-partials
__device__ __align__(16) u32 g_bp[4 * BP_U4];    // packed B frags, uint4-interleaved
__device__ float g_z[B_ROWS * NPAD];             // logits (bias-free, padded)
__device__ float g_psum[GRID_M * NPAD];
__device__ float g_psq[GRID_M * NPAD];
__device__ float g_a[NPAD];                      // rstd*gamma
__device__ float g_b[NPAD];                      // beta - mean*rstd*gamma

// pack bf16x2, memory order (lo,hi)
__device__ __forceinline__ u32 bf16x2(float lo, float hi) {
    u32 r; asm("cvt.rn.bf16x2.f32 %0, %1, %2;" : "=r"(r) : "f"(hi), "f"(lo)); return r;
}
// split a float2 into bf16x2 hi + bf16x2 lo (residual)
__device__ __forceinline__ void split2(float2 v, u32& h, u32& l) {
    h = bf16x2(v.x, v.y);
    float f0 = __uint_as_float(h << 16);
    float f1 = __uint_as_float(h & 0xFFFF0000u);
    l = bf16x2(v.x - f0, v.y - f1);
}
// D += A(16x16 bf16) * B(16x8 bf16), fp32 accum
__device__ __forceinline__ void mma16816(float* c, const u32* a, u32 b0, u32 b1) {
    asm volatile(
        "mma.sync.aligned.m16n8k16.row.col.f32.bf16.bf16.f32 "
        "{%0,%1,%2,%3}, {%4,%5,%6,%7}, {%8,%9}, {%0,%1,%2,%3};"
        : "+f"(c[0]), "+f"(c[1]), "+f"(c[2]), "+f"(c[3])
        : "r"(a[0]), "r"(a[1]), "r"(a[2]), "r"(a[3]), "r"(b0), "r"(b1));
}
__device__ __forceinline__ u32 smem_u32(const void* p) {
    u32 a;
    asm("{ .reg .u64 t; cvta.to.shared.u64 t, %1; cvt.u32.u64 %0, t; }" : "=r"(a) : "l"(p));
    return a;
}
#define CP_ASYNC16(dst, src) \
    asm volatile("cp.async.cg.shared.global [%0], [%1], 16;" :: "r"(dst), "l"(src) : "memory")
#define CP_COMMIT() asm volatile("cp.async.commit_group;" ::: "memory")
#define CP_WAIT(n)  asm volatile("cp.async.wait_group %0;" :: "n"(n) : "memory")

// ============================================================
// wc1: j-partial Wc[a][k] = sum over 192 j's of W_attr[a][j]*W_embed[j][k]
// grid (6 k-blocks, 16 a-groups, 4 j-quarters), 128 threads
// ============================================================
__global__ __launch_bounds__(128) void wc1_kernel(const float* __restrict__ W_embed,
                                                  const float* __restrict__ W_attr) {
    __shared__ float s_wa[4 * 192];
    const int k  = blockIdx.x * 128 + threadIdx.x;
    const int a0 = blockIdx.y * 4;
    const int j0 = blockIdx.z * 192;

    for (int i = threadIdx.x; i < 4 * 192; i += 128) {
        int aa = i / 192, j = i - aa * 192;
        int a  = a0 + aa;
        s_wa[i] = (a < ATTRS) ? W_attr[a * DIM + j0 + j] : 0.0f;
    }
    __syncthreads();

    float acc0 = 0.f, acc1 = 0.f, acc2 = 0.f, acc3 = 0.f;
#pragma unroll 16
    for (int j = 0; j < 192; ++j) {
        float we = W_embed[(size_t)(j0 + j) * DIM + k];
        acc0 = fmaf(s_wa[j      ], we, acc0);
        acc1 = fmaf(s_wa[192 + j], we, acc1);
        acc2 = fmaf(s_wa[384 + j], we, acc2);
        acc3 = fmaf(s_wa[576 + j], we, acc3);
    }
    float* dst = g_wcp + (size_t)blockIdx.z * NPAD * DIM;
    dst[(a0 + 0) * DIM + k] = acc0;
    dst[(a0 + 1) * DIM + k] = acc1;
    dst[(a0 + 2) * DIM + k] = acc2;
    dst[(a0 + 3) * DIM + k] = acc3;
}

// ============================================================
// wc2: combine 4 partials, split bf16 hi/lo, scatter into
// fused uint4 B-fragment layout: entry (ks,nt,lane) = {hi0,hi1,lo0,lo1}
// ============================================================
__global__ __launch_bounds__(256) void wc2_kernel() {
    int idx = blockIdx.x * 256 + threadIdx.x;     // 0..24575
    if (idx >= NPAD * DIM / 2) return;
    int n  = idx / 384;                           // 0..63
    int kp = idx - n * 384;
    int k  = kp * 2;
    size_t i0 = (size_t)n * DIM + k;
    const size_t S = (size_t)NPAD * DIM;
    float s0 = g_wcp[i0]     + g_wcp[S + i0]     + g_wcp[2*S + i0]     + g_wcp[3*S + i0];
    float s1 = g_wcp[i0 + 1] + g_wcp[S + i0 + 1] + g_wcp[2*S + i0 + 1] + g_wcp[3*S + i0 + 1];
    u32 h = bf16x2(s0, s1);
    float f0 = __uint_as_float(h << 16);
    float f1 = __uint_as_float(h & 0xFFFF0000u);
    u32 l = bf16x2(s0 - f0, s1 - f1);

    int ks = k >> 4;
    int hh = (k >> 3) & 1;
    int t  = (n & 7) * 4 + ((k & 7) >> 1);
    int nt = n >> 3;
    int o4 = ((ks * 8 + nt) * 32 + t) * 4;
    g_bp[o4 + hh]     = h;
    g_bp[o4 + 2 + hh] = l;
}

// ============================================================
// GEMM: z = x @ Wc^T via mma.sync bf16 hi/lo split (3 products).
// grid 128, 256 threads = 8 warps; warp w owns rows [w*16,+16).
// B staged via cp.async in 2 halves overlapped with compute.
// A from gmem fp32 at prefetch depth 4, split in registers.
// ============================================================
extern __shared__ __align__(16) char dsm[];

// one k-step of the mainloop (inlined; no macro to avoid shadowing)
__device__ __forceinline__ void kstep(int ks, float2 (&pf)[4][4],
                                      const float* xr0, const float* xr8,
                                      const uint4* sb, int lane,
                                      float (&acc)[8][4]) {
    float2 c0 = pf[ks & 3][0], c1 = pf[ks & 3][1];
    float2 c2 = pf[ks & 3][2], c3 = pf[ks & 3][3];
    if (ks + 4 < NKS) {
        int kc = (ks + 4) * 16;
        pf[ks & 3][0] = *(const float2*)(xr0 + kc);
        pf[ks & 3][1] = *(const float2*)(xr0 + kc + 8);
        pf[ks & 3][2] = *(const float2*)(xr8 + kc);
        pf[ks & 3][3] = *(const float2*)(xr8 + kc + 8);
    }
    // frag order: a0=(r,k0..7) a1=(r+8,k0..7) a2=(r,k8..15) a3=(r+8,k8..15)
    u32 ah[4], al[4];
    split2(c0, ah[0], al[0]);
    split2(c2, ah[1], al[1]);
    split2(c1, ah[2], al[2]);
    split2(c3, ah[3], al[3]);
    const uint4* bp = sb + ks * 256 + lane;
#pragma unroll
    for (int nt = 0; nt < 8; ++nt) {
        uint4 b = bp[nt * 32];
        mma16816(acc[nt], ah, b.x, b.y);
        mma16816(acc[nt], ah, b.z, b.w);
        mma16816(acc[nt], al, b.x, b.y);
    }
}

__global__ __launch_bounds__(256) void gemm_kernel(const float* __restrict__ x) {
    const int tid  = threadIdx.x;
    const int warp = tid >> 5, lane = tid & 31;

    // ---- stage packed B via cp.async: 2 halves of 6144 uint4 ----
    {
        const u32 sbase = smem_u32(dsm);
        const uint4* src = (const uint4*)g_bp;
#pragma unroll
        for (int i = 0; i < 24; ++i) {
            int idx = tid + i * 256;
            CP_ASYNC16(sbase + idx * 16, src + idx);
        }
        CP_COMMIT();
#pragma unroll
        for (int i = 0; i < 24; ++i) {
            int idx = 6144 + tid + i * 256;
            CP_ASYNC16(sbase + idx * 16, src + idx);
        }
        CP_COMMIT();
    }
    const uint4* sb = (const uint4*)dsm;   // [(ks*8+nt)*32 + lane] = {hi0,hi1,lo0,lo1}

    const int r0 = blockIdx.x * 128 + warp * 16 + (lane >> 2);
    const float* xr0 = x + (size_t)r0 * DIM + (lane & 3) * 2;
    const float* xr8 = xr0 + 8 * DIM;

    float acc[8][4];
#pragma unroll
    for (int i = 0; i < 8; ++i)
#pragma unroll
        for (int j = 0; j < 4; ++j) acc[i][j] = 0.0f;

    // A fragment prefetch, depth 4
    float2 pf[4][4];
#pragma unroll
    for (int p = 0; p < 4; ++p) {
        int kc = p * 16;
        pf[p][0] = *(const float2*)(xr0 + kc);
        pf[p][1] = *(const float2*)(xr0 + kc + 8);
        pf[p][2] = *(const float2*)(xr8 + kc);
        pf[p][3] = *(const float2*)(xr8 + kc + 8);
    }

    CP_WAIT(1);            // first half of B resident
    __syncthreads();

#pragma unroll 4
    for (int ks = 0; ks < 24; ++ks)
        kstep(ks, pf, xr0, xr8, sb, lane, acc);

    CP_WAIT(0);            // second half of B resident
    __syncthreads();

#pragma unroll 4
    for (int ks = 24; ks < NKS; ++ks)
        kstep(ks, pf, xr0, xr8, sb, lane, acc);

    // ---- epilogue: store z + BN partials (reuse smem) ----
    __syncthreads();
    float* ssum = (float*)dsm;
    float* ssq  = ssum + NPAD;
    if (tid < 2 * NPAD) ssum[tid] = 0.0f;
    __syncthreads();

    float* zr = g_z + (size_t)r0 * NPAD;
#pragma unroll
    for (int nt = 0; nt < 8; ++nt) {
        int n0 = nt * 8 + (lane & 3) * 2;
        *(float2*)(zr + n0)            = make_float2(acc[nt][0], acc[nt][1]);
        *(float2*)(zr + 8 * NPAD + n0) = make_float2(acc[nt][2], acc[nt][3]);
        float s0 = acc[nt][0] + acc[nt][2];
        float s1 = acc[nt][1] + acc[nt][3];
        float q0 = fmaf(acc[nt][0], acc[nt][0], acc[nt][2] * acc[nt][2]);
        float q1 = fmaf(acc[nt][1], acc[nt][1], acc[nt][3] * acc[nt][3]);
#pragma unroll
        for (int m = 4; m <= 16; m <<= 1) {
            s0 += __shfl_xor_sync(0xffffffffu, s0, m);
            s1 += __shfl_xor_sync(0xffffffffu, s1, m);
            q0 += __shfl_xor_sync(0xffffffffu, q0, m);
            q1 += __shfl_xor_sync(0xffffffffu, q1, m);
        }
        if (lane < 4) {
            atomicAdd(&ssum[n0], s0);     atomicAdd(&ssum[n0 + 1], s1);
            atomicAdd(&ssq[n0], q0);      atomicAdd(&ssq[n0 + 1], q1);
        }
    }
    __syncthreads();
    if (tid < NPAD) {
        g_psum[blockIdx.x * NPAD + tid] = ssum[tid];
        g_psq[blockIdx.x * NPAD + tid]  = ssq[tid];
    }
}

// ============================================================
// stats: one block per column n (64 blocks, 128 threads)
// ============================================================
__global__ __launch_bounds__(128) void stats_kernel(const float* __restrict__ gamma,
                                                    const float* __restrict__ beta) {
    __shared__ float ss[4], sq[4];
    const int n = blockIdx.x;           // 0..63
    const int t = threadIdx.x;          // 0..127
    float s = g_psum[t * NPAD + n];
    float q = g_psq[t * NPAD + n];
#pragma unroll
    for (int m = 16; m >= 1; m >>= 1) {
        s += __shfl_xor_sync(0xffffffffu, s, m);
        q += __shfl_xor_sync(0xffffffffu, q, m);
    }
    if ((t & 31) == 0) { ss[t >> 5] = s; sq[t >> 5] = q; }
    __syncthreads();
    if (t == 0) {
        float S = ss[0] + ss[1] + ss[2] + ss[3];
        float Q = sq[0] + sq[1] + sq[2] + sq[3];
        const float inv = 1.0f / (float)B_ROWS;
        float mean = S * inv;
        float var  = Q * inv - mean * mean;
        float rstd = rsqrtf(var + BN_EPS);
        float gm = (n < ATTRS) ? gamma[n] : 0.0f;
        float bt = (n < ATTRS) ? beta[n]  : 0.0f;
        float a = rstd * gm;
        g_a[n] = a;
        g_b[n] = bt - mean * a;
    }
}

// ============================================================
// norm: y = z*a[n] + b[n] -> d_out [B,51]
// 204*512*8 = 835584 = 16384*51 exactly
// ============================================================
__global__ __launch_bounds__(512) void norm_kernel(float* __restrict__ out) {
    const int b0 = blockIdx.x * 512 + threadIdx.x;
#pragma unroll
    for (int i = 0; i < 8; ++i) {
        int idx = b0 + i * 104448;
        int row = idx / ATTRS;
        int n   = idx - row * ATTRS;
        out[idx] = fmaf(g_z[(size_t)row * NPAD + n], g_a[n], g_b[n]);
    }
}

// ============================================================
extern "C" void kernel_launch(void* const* d_in, const int* in_sizes, int n_in,
                              void* d_out, int out_size) {
    const float* x       = (const float*)d_in[0];
    const float* W_embed = (const float*)d_in[1];
    // d_in[2] = b_embed  (cancelled exactly by BatchNorm mean-subtraction)
    const float* W_attr  = (const float*)d_in[3];
    // d_in[4] = b_attr   (cancelled exactly by BatchNorm mean-subtraction)
    const float* gamma   = (const float*)d_in[5];
    const float* beta    = (const float*)d_in[6];
    float* out = (float*)d_out;

    cudaFuncSetAttribute(gemm_kernel, cudaFuncAttributeMaxDynamicSharedMemorySize, SMEM_DYN);

    wc1_kernel<<<dim3(6, 16, 4), 128>>>(W_embed, W_attr);
    wc2_kernel<<<96, 256>>>();
    gemm_kernel<<<GRID_M, 256, SMEM_DYN>>>(x);
    stats_kernel<<<NPAD, 128>>>(gamma, beta);
    norm_kernel<<<204, 512>>>(out);
}